// round 15
// baseline (speedup 1.0000x reference)
#include <cuda_runtime.h>
#include <cuda_fp16.h>
#include <cstdint>

#define N_NODES 100000
#define N_EDGES 1600000
#define IN_DIM  128
#define HID     64
#define SZ      (N_NODES * HID)
#define SCAN_B  1024
#define NSCAN   ((N_NODES + SCAN_B - 1) / SCAN_B)   // 98
#define PGRID   888   // 6 blocks/SM x 148 SMs; <= residency on 148- and 152-SM parts

typedef unsigned long long ull;

// Scratch (device globals; left zeroed after every call -> deterministic)
__device__ int    g_cnt[N_NODES];
__device__ int    g_pos[N_NODES];
__device__ int    g_roff[N_NODES];
__device__ int    g_bsum[NSCAN];
__device__ int    g_boff[NSCAN];
__device__ int    g_scan_done;
__device__ int    g_gbar[3];              // grid barriers (zeroed by scanA)
__device__ uint2  g_sw[N_EDGES];          // (src, w-bits fp32) grouped by tgt
// Double-buffered fp16 mirror of h: layer l READS buf[l&1], WRITES buf[(l+1)&1].
__device__ __half g_h16[2][SZ];

// ---- packed f32x2 helpers ----
#define FMA2(d, a, b, c) \
    asm("fma.rn.f32x2 %0, %1, %2, %3;" : "=l"(d) : "l"(a), "l"(b), "l"(c))

__device__ __forceinline__ ull pack2(float lo, float hi) {
    ull r;
    unsigned int l = __float_as_uint(lo), h = __float_as_uint(hi);
    asm("mov.b64 %0, {%1, %2};" : "=l"(r) : "r"(l), "r"(h));
    return r;
}
__device__ __forceinline__ float2 unpack2(ull v) {
    float2 f; unsigned int l, h;
    asm("mov.b64 {%0, %1}, %2;" : "=r"(l), "=r"(h) : "l"(v));
    f.x = __uint_as_float(l); f.y = __uint_as_float(h);
    return f;
}

// XOR swizzle for k-major A tiles (conflict-free both phases; proven R5-R14)
#define ASW(k)       ((((k) >> 3) & 7) << 2)
#define APAD 68
#define AIDX2(k, n)  ((k) * APAD + ((n) ^ ASW(k)))

// fp16x8 -> 8 fp32 FMA into acc
__device__ __forceinline__ void hfma8(uint4 v, float w, float* a) {
    float2 f;
    f = __half22float2(*(const __half2*)&v.x); a[0] = fmaf(f.x, w, a[0]); a[1] = fmaf(f.y, w, a[1]);
    f = __half22float2(*(const __half2*)&v.y); a[2] = fmaf(f.x, w, a[2]); a[3] = fmaf(f.y, w, a[3]);
    f = __half22float2(*(const __half2*)&v.z); a[4] = fmaf(f.x, w, a[4]); a[5] = fmaf(f.y, w, a[5]);
    f = __half22float2(*(const __half2*)&v.w); a[6] = fmaf(f.x, w, a[6]); a[7] = fmaf(f.y, w, a[7]);
}

__device__ __forceinline__ void store_h16(__half* dst, int gn, int c, float4 ov) {
    __half2 lo = __floats2half2_rn(ov.x, ov.y);
    __half2 hi = __floats2half2_rn(ov.z, ov.w);
    uint2 u;
    u.x = *reinterpret_cast<unsigned*>(&lo);
    u.y = *reinterpret_cast<unsigned*>(&hi);
    *reinterpret_cast<uint2*>((char*)dst + (size_t)gn * 128 + c * 8) = u;
}

// Grid-wide spin barrier. Safe: grid == PGRID <= max co-resident blocks and
// the stream is idle when this kernel starts, so ALL blocks are resident
// before any spin. Counters zeroed by scanA each call.
__device__ __forceinline__ void grid_bar(int slot) {
    __syncthreads();
    if (threadIdx.x == 0) {
        __threadfence();
        atomicAdd(&g_gbar[slot], 1);
        while (*(volatile int*)&g_gbar[slot] < PGRID) { }
        __threadfence();
    }
    __syncthreads();
}

// ============================================================================
// Kernel 1: h0 = relu(x @ Wi + bi) (fp32 out + fp16 mirror buf0) + fused
// CSR target histogram. 64-node blocks, W via __ldg, 6 blocks/SM. (R13 form)
// ============================================================================
__global__ void __launch_bounds__(256, 6) gemm_in_kernel(
    const float* __restrict__ x, const float* __restrict__ Wi,
    const float* __restrict__ bi, const int* __restrict__ tgt,
    float* __restrict__ out)
{
    __shared__ float Ash[IN_DIM * APAD];   // k-major [128][68], 34816 B

    const int tid = threadIdx.x;
    const int nbase = blockIdx.x * 64;

    {
        int ebase = blockIdx.x * 1024;
        #pragma unroll
        for (int o = 0; o < 4; o++) {
            int e = ebase + o * 256 + tid;
            if (e < N_EDGES) atomicAdd(&g_cnt[tgt[e]], 1);
        }
    }

    for (int i = tid; i < 1024; i += 256) {
        int k8 = i >> 6;
        int n  = i & 63;
        int gn = nbase + n;
        float4 v0 = make_float4(0.f,0.f,0.f,0.f), v1 = v0;
        if (gn < N_NODES) {
            const float4* xp = (const float4*)(x + (size_t)gn * IN_DIM + k8 * 8);
            v0 = __ldg(xp); v1 = __ldg(xp + 1);
        }
        int k = k8 * 8;
        Ash[AIDX2(k+0, n)] = v0.x; Ash[AIDX2(k+1, n)] = v0.y;
        Ash[AIDX2(k+2, n)] = v0.z; Ash[AIDX2(k+3, n)] = v0.w;
        Ash[AIDX2(k+4, n)] = v1.x; Ash[AIDX2(k+5, n)] = v1.y;
        Ash[AIDX2(k+6, n)] = v1.z; Ash[AIDX2(k+7, n)] = v1.w;
    }
    __syncthreads();

    const int r = tid >> 4;
    const int c = tid & 15;

    float4 bv = __ldg((const float4*)(bi + c * 4));
    ull acc[2][4];
    #pragma unroll
    for (int q = 0; q < 2; q++) {
        acc[q][0] = pack2(bv.x, bv.x); acc[q][1] = pack2(bv.y, bv.y);
        acc[q][2] = pack2(bv.z, bv.z); acc[q][3] = pack2(bv.w, bv.w);
    }

    #pragma unroll 8
    for (int k = 0; k < IN_DIM; k++) {
        ulonglong2 aA = *(const ulonglong2*)&Ash[k * APAD + ((r * 4) ^ ASW(k))];
        float4 wv = __ldg((const float4*)(Wi + k * HID + c * 4));
        ull w0 = pack2(wv.x, wv.x), w1 = pack2(wv.y, wv.y);
        ull w2 = pack2(wv.z, wv.z), w3 = pack2(wv.w, wv.w);
        FMA2(acc[0][0], aA.x, w0, acc[0][0]);
        FMA2(acc[0][1], aA.x, w1, acc[0][1]);
        FMA2(acc[0][2], aA.x, w2, acc[0][2]);
        FMA2(acc[0][3], aA.x, w3, acc[0][3]);
        FMA2(acc[1][0], aA.y, w0, acc[1][0]);
        FMA2(acc[1][1], aA.y, w1, acc[1][1]);
        FMA2(acc[1][2], aA.y, w2, acc[1][2]);
        FMA2(acc[1][3], aA.y, w3, acc[1][3]);
    }

    #pragma unroll
    for (int q = 0; q < 2; q++) {
        float2 e0 = unpack2(acc[q][0]), e1 = unpack2(acc[q][1]);
        float2 e2 = unpack2(acc[q][2]), e3 = unpack2(acc[q][3]);
        int n0 = nbase + r * 4 + 2 * q;
        if (n0 < N_NODES) {
            float4 o = make_float4(fmaxf(e0.x,0.f), fmaxf(e1.x,0.f),
                                   fmaxf(e2.x,0.f), fmaxf(e3.x,0.f));
            *(float4*)(out + (size_t)n0 * HID + c * 4) = o;
            store_h16(g_h16[0], n0, c, o);
        }
        if (n0 + 1 < N_NODES) {
            float4 o = make_float4(fmaxf(e0.y,0.f), fmaxf(e1.y,0.f),
                                   fmaxf(e2.y,0.f), fmaxf(e3.y,0.f));
            *(float4*)(out + (size_t)(n0+1) * HID + c * 4) = o;
            store_h16(g_h16[0], n0 + 1, c, o);
        }
    }
}

// ============================================================================
// scanA (+fused scanB, self-cleaning; also zeroes the grid barriers)
// ============================================================================
__global__ void __launch_bounds__(SCAN_B) scanA_kernel() {
    __shared__ int wsum[32];
    __shared__ int slast;
    const int t = threadIdx.x;
    const int lane = t & 31, wid = t >> 5;
    const int n = blockIdx.x * SCAN_B + t;

    int orig = (n < N_NODES) ? g_cnt[n] : 0;
    int v = orig;
    #pragma unroll
    for (int d = 1; d < 32; d <<= 1) {
        int xv = __shfl_up_sync(0xffffffffu, v, d);
        if (lane >= d) v += xv;
    }
    if (lane == 31) wsum[wid] = v;
    __syncthreads();
    if (wid == 0) {
        int w = wsum[lane];
        #pragma unroll
        for (int d = 1; d < 32; d <<= 1) {
            int xv = __shfl_up_sync(0xffffffffu, w, d);
            if (lane >= d) w += xv;
        }
        wsum[lane] = w;
    }
    __syncthreads();
    int incl = v + (wid ? wsum[wid - 1] : 0);
    if (n < N_NODES) g_roff[n] = incl - orig;
    if (t == SCAN_B - 1) g_bsum[blockIdx.x] = incl;

    __threadfence();
    if (t == 0) slast = (atomicAdd(&g_scan_done, 1) == gridDim.x - 1) ? 1 : 0;
    __syncthreads();
    if (slast && wid == 0) {
        __threadfence();
        int run = 0;
        #pragma unroll
        for (int base = 0; base < NSCAN; base += 32) {
            int idx = base + lane;
            int bv = (idx < NSCAN) ? g_bsum[idx] : 0;
            int sv = bv;
            #pragma unroll
            for (int d = 1; d < 32; d <<= 1) {
                int xv = __shfl_up_sync(0xffffffffu, sv, d);
                if (lane >= d) sv += xv;
            }
            if (idx < NSCAN) g_boff[idx] = run + sv - bv;
            run += __shfl_sync(0xffffffffu, sv, 31);
        }
        if (lane == 0) {
            g_scan_done = 0;
            g_gbar[0] = 0; g_gbar[1] = 0; g_gbar[2] = 0;
        }
    }
}

// ============================================================================
// Layer phase body (R13's proven loop, parameterized by tile index)
// ============================================================================
__device__ __forceinline__ void layer_tile(
    float* Ash, int tile,
    const float* __restrict__ hin, const float* __restrict__ W,
    const float* __restrict__ b, float* __restrict__ out,
    const __half* h16r, __half* h16w, int clear, int tid)
{
    const int nbase = tile * 64;
    const int grp = tid >> 3;
    const int p   = tid & 7;

    #pragma unroll
    for (int o = 0; o < 2; o++) {
        int ln = o * 32 + grp;
        int gn = nbase + ln;
        float a[8] = {0.f,0.f,0.f,0.f,0.f,0.f,0.f,0.f};
        if (gn < N_NODES) {
            int rs = g_roff[gn] + g_boff[gn >> 10];
            int cn = g_cnt[gn];
            if (clear && p == 0) { g_cnt[gn] = 0; g_pos[gn] = 0; }
            const uint2* sw = g_sw + rs;
            const char* hb = (const char*)h16r + p * 16;
            int i = 0;
            for (; i + 4 <= cn; i += 4) {
                uint2 s0 = __ldg(sw + i),     s1 = __ldg(sw + i + 1);
                uint2 s2 = __ldg(sw + i + 2), s3 = __ldg(sw + i + 3);
                uint4 v0 = __ldg((const uint4*)(hb + (size_t)s0.x * 128));
                uint4 v1 = __ldg((const uint4*)(hb + (size_t)s1.x * 128));
                uint4 v2 = __ldg((const uint4*)(hb + (size_t)s2.x * 128));
                uint4 v3 = __ldg((const uint4*)(hb + (size_t)s3.x * 128));
                hfma8(v0, __uint_as_float(s0.y), a);
                hfma8(v1, __uint_as_float(s1.y), a);
                hfma8(v2, __uint_as_float(s2.y), a);
                hfma8(v3, __uint_as_float(s3.y), a);
            }
            if (i < cn) {
                int j1 = (i + 1 < cn) ? i + 1 : cn - 1;
                int j2 = (i + 2 < cn) ? i + 2 : cn - 1;
                uint2 s0 = __ldg(sw + i);
                uint2 s1 = __ldg(sw + j1);
                uint2 s2 = __ldg(sw + j2);
                uint4 v0 = __ldg((const uint4*)(hb + (size_t)s0.x * 128));
                uint4 v1 = __ldg((const uint4*)(hb + (size_t)s1.x * 128));
                uint4 v2 = __ldg((const uint4*)(hb + (size_t)s2.x * 128));
                float w0 = __uint_as_float(s0.y);
                float w1 = (i + 1 < cn) ? __uint_as_float(s1.y) : 0.f;
                float w2 = (i + 2 < cn) ? __uint_as_float(s2.y) : 0.f;
                hfma8(v0, w0, a);
                hfma8(v1, w1, a);
                hfma8(v2, w2, a);
            }
            const float4* hp = (const float4*)(hin + (size_t)gn * HID + p * 8);
            float4 h0 = hp[0], h1 = hp[1];
            a[0]+=h0.x; a[1]+=h0.y; a[2]+=h0.z; a[3]+=h0.w;
            a[4]+=h1.x; a[5]+=h1.y; a[6]+=h1.z; a[7]+=h1.w;
        }
        int k0 = p * 8;
        #pragma unroll
        for (int j = 0; j < 8; j++)
            Ash[AIDX2(k0 + j, ln)] = a[j];
    }
    __syncthreads();

    const int r = tid >> 4;
    const int c = tid & 15;

    float4 bv = __ldg((const float4*)(b + c * 4));
    ull acc[2][4];
    #pragma unroll
    for (int q = 0; q < 2; q++) {
        acc[q][0] = pack2(bv.x, bv.x); acc[q][1] = pack2(bv.y, bv.y);
        acc[q][2] = pack2(bv.z, bv.z); acc[q][3] = pack2(bv.w, bv.w);
    }

    #pragma unroll 8
    for (int k = 0; k < HID; k++) {
        ulonglong2 aA = *(const ulonglong2*)&Ash[k * APAD + ((r * 4) ^ ASW(k))];
        float4 wv = __ldg((const float4*)(W + k * HID + c * 4));
        ull w0 = pack2(wv.x, wv.x), w1 = pack2(wv.y, wv.y);
        ull w2 = pack2(wv.z, wv.z), w3 = pack2(wv.w, wv.w);
        FMA2(acc[0][0], aA.x, w0, acc[0][0]);
        FMA2(acc[0][1], aA.x, w1, acc[0][1]);
        FMA2(acc[0][2], aA.x, w2, acc[0][2]);
        FMA2(acc[0][3], aA.x, w3, acc[0][3]);
        FMA2(acc[1][0], aA.y, w0, acc[1][0]);
        FMA2(acc[1][1], aA.y, w1, acc[1][1]);
        FMA2(acc[1][2], aA.y, w2, acc[1][2]);
        FMA2(acc[1][3], aA.y, w3, acc[1][3]);
    }

    #pragma unroll
    for (int q = 0; q < 2; q++) {
        float2 e0 = unpack2(acc[q][0]), e1 = unpack2(acc[q][1]);
        float2 e2 = unpack2(acc[q][2]), e3 = unpack2(acc[q][3]);
        int n0 = nbase + r * 4 + 2 * q;
        if (n0 < N_NODES) {
            float4 ov = make_float4(fmaxf(e0.x,0.f), fmaxf(e1.x,0.f),
                                    fmaxf(e2.x,0.f), fmaxf(e3.x,0.f));
            *(float4*)(out + (size_t)n0 * HID + c * 4) = ov;
            store_h16(h16w, n0, c, ov);
        }
        if (n0 + 1 < N_NODES) {
            float4 ov = make_float4(fmaxf(e0.y,0.f), fmaxf(e1.y,0.f),
                                    fmaxf(e2.y,0.f), fmaxf(e3.y,0.f));
            *(float4*)(out + (size_t)(n0+1) * HID + c * 4) = ov;
            store_h16(h16w, n0 + 1, c, ov);
        }
    }
    __syncthreads();   // protect Ash before next tile's gather
}

// ============================================================================
// Mega kernel: fill -> bar -> layer1 -> bar -> layer2 -> bar -> layer3.
// Persistent: PGRID blocks, each strides tiles (+PGRID). One launch replaces
// four, eliminating inter-launch drain + wave-quantized tails.
// ============================================================================
#define NTILES ((N_NODES + 63) / 64)   // 1563
__global__ void __launch_bounds__(256, 6) mega_kernel(
    const int* __restrict__ src, const int* __restrict__ tgt,
    const float* __restrict__ ea,
    const float* __restrict__ W1, const float* __restrict__ b1,
    const float* __restrict__ W2, const float* __restrict__ b2,
    const float* __restrict__ W3, const float* __restrict__ b3,
    float* __restrict__ out)
{
    __shared__ float Ash[HID * APAD];   // 17408 B
    const int tid = threadIdx.x;

    // ---- phase 0: fill (atomic slot assignment; R13's proven form) ----
    for (int e = blockIdx.x * 256 + tid; e < N_EDGES; e += PGRID * 256) {
        int t = tgt[e];
        int p = atomicAdd(&g_pos[t], 1);
        int base = g_roff[t] + g_boff[t >> 10];
        g_sw[base + p] = make_uint2((unsigned)src[e], __float_as_uint(ea[e]));
    }
    grid_bar(0);

    // ---- layer 1: reads h0 (out[0..SZ), h16 buf0) -> h1 ----
    for (int tile = blockIdx.x; tile < NTILES; tile += PGRID)
        layer_tile(Ash, tile, out, W1, b1, out + SZ,
                   g_h16[0], g_h16[1], 0, tid);
    grid_bar(1);

    // ---- layer 2 ----
    for (int tile = blockIdx.x; tile < NTILES; tile += PGRID)
        layer_tile(Ash, tile, out + SZ, W2, b2, out + 2 * SZ,
                   g_h16[1], g_h16[0], 0, tid);
    grid_bar(2);

    // ---- layer 3 (clears g_cnt/g_pos for the next call) ----
    for (int tile = blockIdx.x; tile < NTILES; tile += PGRID)
        layer_tile(Ash, tile, out + 2 * SZ, W3, b3, out + 3 * SZ,
                   g_h16[0], g_h16[1], 1, tid);
}

// ============================================================================
// Launch sequence: 3 launches (was 6)
// ============================================================================
extern "C" void kernel_launch(void* const* d_in, const int* in_sizes, int n_in,
                              void* d_out, int out_size)
{
    const float* x  = (const float*)d_in[0];
    const int*   ei = (const int*)d_in[1];
    const float* ea = (const float*)d_in[2];
    const float* Wi = (const float*)d_in[3];
    const float* bi = (const float*)d_in[4];
    const float* W1 = (const float*)d_in[5];
    const float* b1 = (const float*)d_in[6];
    const float* W2 = (const float*)d_in[7];
    const float* b2 = (const float*)d_in[8];
    const float* W3 = (const float*)d_in[9];
    const float* b3 = (const float*)d_in[10];
    float* out = (float*)d_out;

    const int* src = ei;
    const int* tgt = ei + N_EDGES;

    const int NODE_BLOCKS = (N_NODES + 63) / 64;                // 1563

    gemm_in_kernel<<<NODE_BLOCKS, 256>>>(x, Wi, bi, tgt, out);   // 1 (+hist)
    scanA_kernel<<<NSCAN, SCAN_B>>>();                           // 2 (+scanB, bar reset)
    mega_kernel<<<PGRID, 256>>>(src, tgt, ea, W1, b1, W2, b2,    // 3 (fill+3 layers)
                                W3, b3, out);
}

// round 16
// speedup vs baseline: 1.0722x; 1.0722x over previous
#include <cuda_runtime.h>
#include <cuda_fp16.h>
#include <cstdint>

#define N_NODES 100000
#define N_EDGES 1600000
#define IN_DIM  128
#define HID     64
#define SZ      (N_NODES * HID)
#define SCAN_B  1024
#define NSCAN   ((N_NODES + SCAN_B - 1) / SCAN_B)   // 98

typedef unsigned long long ull;

// Scratch (device globals; left zeroed after every call -> deterministic)
__device__ int    g_cnt[N_NODES];
__device__ int    g_pos[N_NODES];
__device__ int    g_roff[N_NODES];
__device__ int    g_bsum[NSCAN];
__device__ int    g_boff[NSCAN];
__device__ int    g_scan_done;
__device__ uint2  g_sw[N_EDGES];          // (src, w-bits fp32) grouped by tgt
// Double-buffered fp16 mirror of h: layer l READS buf[l&1], WRITES buf[(l+1)&1].
__device__ __half g_h16[2][SZ];

// ---- packed f32x2 helpers ----
#define FMA2(d, a, b, c) \
    asm("fma.rn.f32x2 %0, %1, %2, %3;" : "=l"(d) : "l"(a), "l"(b), "l"(c))

__device__ __forceinline__ ull pack2(float lo, float hi) {
    ull r;
    unsigned int l = __float_as_uint(lo), h = __float_as_uint(hi);
    asm("mov.b64 %0, {%1, %2};" : "=l"(r) : "r"(l), "r"(h));
    return r;
}
__device__ __forceinline__ float2 unpack2(ull v) {
    float2 f; unsigned int l, h;
    asm("mov.b64 {%0, %1}, %2;" : "=r"(l), "=r"(h) : "l"(v));
    f.x = __uint_as_float(l); f.y = __uint_as_float(h);
    return f;
}

// XOR swizzle for k-major A tiles (conflict-free both phases; proven R5-R14)
#define ASW(k)       ((((k) >> 3) & 7) << 2)
#define NPAD 132
#define AIDX(k, n)   ((k) * NPAD + ((n) ^ ASW(k)))    // 128-node tiles (gemm_in)
#define APAD 68
#define AIDX2(k, n)  ((k) * APAD + ((n) ^ ASW(k)))    // 64-node tiles (layer)

// fp16x8 -> 8 fp32 FMA into acc
__device__ __forceinline__ void hfma8(uint4 v, float w, float* a) {
    float2 f;
    f = __half22float2(*(const __half2*)&v.x); a[0] = fmaf(f.x, w, a[0]); a[1] = fmaf(f.y, w, a[1]);
    f = __half22float2(*(const __half2*)&v.y); a[2] = fmaf(f.x, w, a[2]); a[3] = fmaf(f.y, w, a[3]);
    f = __half22float2(*(const __half2*)&v.z); a[4] = fmaf(f.x, w, a[4]); a[5] = fmaf(f.y, w, a[5]);
    f = __half22float2(*(const __half2*)&v.w); a[6] = fmaf(f.x, w, a[6]); a[7] = fmaf(f.y, w, a[7]);
}

__device__ __forceinline__ void store_h16(__half* dst, int gn, int c, float4 ov) {
    __half2 lo = __floats2half2_rn(ov.x, ov.y);
    __half2 hi = __floats2half2_rn(ov.z, ov.w);
    uint2 u;
    u.x = *reinterpret_cast<unsigned*>(&lo);
    u.y = *reinterpret_cast<unsigned*>(&hi);
    *reinterpret_cast<uint2*>((char*)dst + (size_t)gn * 128 + c * 8) = u;
}

// ============================================================================
// Kernel 1: h0 = relu(x @ Wi + bi) + fused CSR histogram.
// RESTORED 128-node tile with 8-node x 4-col thread tiles (16 FMA2 per
// ~23 instr/k — R13's 4x4 rebuild measured 74us at issue=36% because W
// traffic per FMA doubled). A-only smem (67.6 KB dynamic) + W via __ldg
// -> 3 blocks/SM (vs 2 for the old 100 KB A+W version).
// ============================================================================
__global__ void __launch_bounds__(256) gemm_in_kernel(
    const float* __restrict__ x, const float* __restrict__ Wi,
    const float* __restrict__ bi, const int* __restrict__ tgt,
    float* __restrict__ out)
{
    extern __shared__ float Ash[];         // k-major [128][132], 67584 B

    const int tid = threadIdx.x;
    const int nbase = blockIdx.x * 128;

    // fused histogram chunk (2048 edges/block, 782 blocks covers 1.6M)
    {
        int ebase = blockIdx.x * 2048;
        #pragma unroll
        for (int o = 0; o < 8; o++) {
            int e = ebase + o * 256 + tid;
            if (e < N_EDGES) atomicAdd(&g_cnt[tgt[e]], 1);
        }
    }

    // load x tile transposed into swizzled k-major A
    for (int i = tid; i < 2048; i += 256) {
        int k8 = i >> 7;           // 0..15
        int n  = i & 127;
        int gn = nbase + n;
        float4 v0 = make_float4(0.f,0.f,0.f,0.f), v1 = v0;
        if (gn < N_NODES) {
            const float4* xp = (const float4*)(x + (size_t)gn * IN_DIM + k8 * 8);
            v0 = __ldg(xp); v1 = __ldg(xp + 1);
        }
        int k = k8 * 8;
        Ash[AIDX(k+0, n)] = v0.x; Ash[AIDX(k+1, n)] = v0.y;
        Ash[AIDX(k+2, n)] = v0.z; Ash[AIDX(k+3, n)] = v0.w;
        Ash[AIDX(k+4, n)] = v1.x; Ash[AIDX(k+5, n)] = v1.y;
        Ash[AIDX(k+6, n)] = v1.z; Ash[AIDX(k+7, n)] = v1.w;
    }
    __syncthreads();

    const int r = tid >> 4;    // nodes r*8 .. r*8+7
    const int c = tid & 15;    // cols  c*4 .. c*4+3

    float4 bv = __ldg((const float4*)(bi + c * 4));
    ull acc[4][4];
    #pragma unroll
    for (int p = 0; p < 4; p++) {
        acc[p][0] = pack2(bv.x, bv.x); acc[p][1] = pack2(bv.y, bv.y);
        acc[p][2] = pack2(bv.z, bv.z); acc[p][3] = pack2(bv.w, bv.w);
    }

    #pragma unroll 8
    for (int k = 0; k < IN_DIM; k++) {
        int q0 = (r * 8) ^ ASW(k);
        ulonglong2 aA = *(const ulonglong2*)&Ash[k * NPAD + q0];
        ulonglong2 aB = *(const ulonglong2*)&Ash[k * NPAD + (q0 ^ 4)];
        float4 wv = __ldg((const float4*)(Wi + k * HID + c * 4));   // L1-hot
        ull w0 = pack2(wv.x, wv.x), w1 = pack2(wv.y, wv.y);
        ull w2 = pack2(wv.z, wv.z), w3 = pack2(wv.w, wv.w);
        ull ap_[4] = {aA.x, aA.y, aB.x, aB.y};
        #pragma unroll
        for (int p = 0; p < 4; p++) {
            FMA2(acc[p][0], ap_[p], w0, acc[p][0]);
            FMA2(acc[p][1], ap_[p], w1, acc[p][1]);
            FMA2(acc[p][2], ap_[p], w2, acc[p][2]);
            FMA2(acc[p][3], ap_[p], w3, acc[p][3]);
        }
    }

    #pragma unroll
    for (int p = 0; p < 4; p++) {
        float2 e0 = unpack2(acc[p][0]), e1 = unpack2(acc[p][1]);
        float2 e2 = unpack2(acc[p][2]), e3 = unpack2(acc[p][3]);
        int n0 = nbase + r * 8 + 2 * p;
        if (n0 < N_NODES) {
            float4 o = make_float4(fmaxf(e0.x,0.f), fmaxf(e1.x,0.f),
                                   fmaxf(e2.x,0.f), fmaxf(e3.x,0.f));
            *(float4*)(out + (size_t)n0 * HID + c * 4) = o;
            store_h16(g_h16[0], n0, c, o);
        }
        if (n0 + 1 < N_NODES) {
            float4 o = make_float4(fmaxf(e0.y,0.f), fmaxf(e1.y,0.f),
                                   fmaxf(e2.y,0.f), fmaxf(e3.y,0.f));
            *(float4*)(out + (size_t)(n0+1) * HID + c * 4) = o;
            store_h16(g_h16[0], n0 + 1, c, o);
        }
    }
}

// ============================================================================
// scanA (+fused scanB, self-cleaning)  — R13 verbatim
// ============================================================================
__global__ void __launch_bounds__(SCAN_B) scanA_kernel() {
    __shared__ int wsum[32];
    __shared__ int slast;
    const int t = threadIdx.x;
    const int lane = t & 31, wid = t >> 5;
    const int n = blockIdx.x * SCAN_B + t;

    int orig = (n < N_NODES) ? g_cnt[n] : 0;
    int v = orig;
    #pragma unroll
    for (int d = 1; d < 32; d <<= 1) {
        int xv = __shfl_up_sync(0xffffffffu, v, d);
        if (lane >= d) v += xv;
    }
    if (lane == 31) wsum[wid] = v;
    __syncthreads();
    if (wid == 0) {
        int w = wsum[lane];
        #pragma unroll
        for (int d = 1; d < 32; d <<= 1) {
            int xv = __shfl_up_sync(0xffffffffu, w, d);
            if (lane >= d) w += xv;
        }
        wsum[lane] = w;
    }
    __syncthreads();
    int incl = v + (wid ? wsum[wid - 1] : 0);
    if (n < N_NODES) g_roff[n] = incl - orig;
    if (t == SCAN_B - 1) g_bsum[blockIdx.x] = incl;

    __threadfence();
    if (t == 0) slast = (atomicAdd(&g_scan_done, 1) == gridDim.x - 1) ? 1 : 0;
    __syncthreads();
    if (slast && wid == 0) {
        __threadfence();
        int run = 0;
        #pragma unroll
        for (int base = 0; base < NSCAN; base += 32) {
            int idx = base + lane;
            int bv = (idx < NSCAN) ? g_bsum[idx] : 0;
            int sv = bv;
            #pragma unroll
            for (int d = 1; d < 32; d <<= 1) {
                int xv = __shfl_up_sync(0xffffffffu, sv, d);
                if (lane >= d) sv += xv;
            }
            if (idx < NSCAN) g_boff[idx] = run + sv - bv;
            run += __shfl_sync(0xffffffffu, sv, 31);
        }
        if (lane == 0) g_scan_done = 0;
    }
}

// fill — R13 verbatim (atomic slot assignment)
__global__ void __launch_bounds__(256) fill_kernel(
    const int* __restrict__ src, const int* __restrict__ tgt,
    const float* __restrict__ ea) {
    int e = blockIdx.x * 256 + threadIdx.x;
    if (e >= N_EDGES) return;
    int t = tgt[e];
    int p = atomicAdd(&g_pos[t], 1);
    int base = g_roff[t] + g_boff[t >> 10];
    g_sw[base + p] = make_uint2((unsigned)src[e], __float_as_uint(ea[e]));
}

// ============================================================================
// Fused layer — R13 verbatim (best measured ~50us): 8 threads/node fp32
// gather, 4-deep uint4 batches, clamped tail; W via __ldg; swizzled A tile.
// ============================================================================
__global__ void __launch_bounds__(256, 6) layer_kernel(
    const float* __restrict__ hin, const float* __restrict__ W,
    const float* __restrict__ b, float* __restrict__ out,
    int lparity, int clear)
{
    __shared__ float Ash[HID * APAD];   // k-major [64][68], 17408 B

    const __half* h16r = g_h16[lparity];
    __half*       h16w = g_h16[lparity ^ 1];

    const int tid = threadIdx.x;
    const int nbase = blockIdx.x * 64;

    const int grp = tid >> 3;   // 0..31 node slot
    const int p   = tid & 7;    // k-slot: k = p*8 .. p*8+7

    #pragma unroll
    for (int o = 0; o < 2; o++) {
        int ln = o * 32 + grp;
        int gn = nbase + ln;
        float a[8] = {0.f,0.f,0.f,0.f,0.f,0.f,0.f,0.f};
        if (gn < N_NODES) {
            int rs = g_roff[gn] + g_boff[gn >> 10];
            int cn = g_cnt[gn];
            if (clear && p == 0) { g_cnt[gn] = 0; g_pos[gn] = 0; }
            const uint2* sw = g_sw + rs;
            const char* hb = (const char*)h16r + p * 16;
            int i = 0;
            for (; i + 4 <= cn; i += 4) {
                uint2 s0 = __ldg(sw + i),     s1 = __ldg(sw + i + 1);
                uint2 s2 = __ldg(sw + i + 2), s3 = __ldg(sw + i + 3);
                uint4 v0 = __ldg((const uint4*)(hb + (size_t)s0.x * 128));
                uint4 v1 = __ldg((const uint4*)(hb + (size_t)s1.x * 128));
                uint4 v2 = __ldg((const uint4*)(hb + (size_t)s2.x * 128));
                uint4 v3 = __ldg((const uint4*)(hb + (size_t)s3.x * 128));
                hfma8(v0, __uint_as_float(s0.y), a);
                hfma8(v1, __uint_as_float(s1.y), a);
                hfma8(v2, __uint_as_float(s2.y), a);
                hfma8(v3, __uint_as_float(s3.y), a);
            }
            if (i < cn) {           // clamped 3-wide tail (w=0 padding)
                int j1 = (i + 1 < cn) ? i + 1 : cn - 1;
                int j2 = (i + 2 < cn) ? i + 2 : cn - 1;
                uint2 s0 = __ldg(sw + i);
                uint2 s1 = __ldg(sw + j1);
                uint2 s2 = __ldg(sw + j2);
                uint4 v0 = __ldg((const uint4*)(hb + (size_t)s0.x * 128));
                uint4 v1 = __ldg((const uint4*)(hb + (size_t)s1.x * 128));
                uint4 v2 = __ldg((const uint4*)(hb + (size_t)s2.x * 128));
                float w0 = __uint_as_float(s0.y);
                float w1 = (i + 1 < cn) ? __uint_as_float(s1.y) : 0.f;
                float w2 = (i + 2 < cn) ? __uint_as_float(s2.y) : 0.f;
                hfma8(v0, w0, a);
                hfma8(v1, w1, a);
                hfma8(v2, w2, a);
            }
            // exact fp32 self-term
            const float4* hp = (const float4*)(hin + (size_t)gn * HID + p * 8);
            float4 h0 = hp[0], h1 = hp[1];
            a[0]+=h0.x; a[1]+=h0.y; a[2]+=h0.z; a[3]+=h0.w;
            a[4]+=h1.x; a[5]+=h1.y; a[6]+=h1.z; a[7]+=h1.w;
        }
        int k0 = p * 8;
        #pragma unroll
        for (int j = 0; j < 8; j++)
            Ash[AIDX2(k0 + j, ln)] = a[j];
    }
    __syncthreads();

    // ---- GEMM: h_next = relu(A @ W + b), thread tile 4 nodes x 4 cols ----
    const int r = tid >> 4;
    const int c = tid & 15;

    float4 bv = __ldg((const float4*)(b + c * 4));
    ull acc[2][4];
    #pragma unroll
    for (int q = 0; q < 2; q++) {
        acc[q][0] = pack2(bv.x, bv.x); acc[q][1] = pack2(bv.y, bv.y);
        acc[q][2] = pack2(bv.z, bv.z); acc[q][3] = pack2(bv.w, bv.w);
    }

    #pragma unroll 8
    for (int k = 0; k < HID; k++) {
        ulonglong2 aA = *(const ulonglong2*)&Ash[k * APAD + ((r * 4) ^ ASW(k))];
        float4 wv = __ldg((const float4*)(W + k * HID + c * 4));  // L1-hot
        ull w0 = pack2(wv.x, wv.x), w1 = pack2(wv.y, wv.y);
        ull w2 = pack2(wv.z, wv.z), w3 = pack2(wv.w, wv.w);
        FMA2(acc[0][0], aA.x, w0, acc[0][0]);
        FMA2(acc[0][1], aA.x, w1, acc[0][1]);
        FMA2(acc[0][2], aA.x, w2, acc[0][2]);
        FMA2(acc[0][3], aA.x, w3, acc[0][3]);
        FMA2(acc[1][0], aA.y, w0, acc[1][0]);
        FMA2(acc[1][1], aA.y, w1, acc[1][1]);
        FMA2(acc[1][2], aA.y, w2, acc[1][2]);
        FMA2(acc[1][3], aA.y, w3, acc[1][3]);
    }

    #pragma unroll
    for (int q = 0; q < 2; q++) {
        float2 e0 = unpack2(acc[q][0]), e1 = unpack2(acc[q][1]);
        float2 e2 = unpack2(acc[q][2]), e3 = unpack2(acc[q][3]);
        int n0 = nbase + r * 4 + 2 * q;
        if (n0 < N_NODES) {
            float4 ov = make_float4(fmaxf(e0.x,0.f), fmaxf(e1.x,0.f),
                                    fmaxf(e2.x,0.f), fmaxf(e3.x,0.f));
            *(float4*)(out + (size_t)n0 * HID + c * 4) = ov;
            store_h16(h16w, n0, c, ov);
        }
        if (n0 + 1 < N_NODES) {
            float4 ov = make_float4(fmaxf(e0.y,0.f), fmaxf(e1.y,0.f),
                                    fmaxf(e2.y,0.f), fmaxf(e3.y,0.f));
            *(float4*)(out + (size_t)(n0+1) * HID + c * 4) = ov;
            store_h16(h16w, n0 + 1, c, ov);
        }
    }
}

// ============================================================================
// Launch sequence (6 launches; layer1 is launch #4 -> ncu captures it)
// ============================================================================
extern "C" void kernel_launch(void* const* d_in, const int* in_sizes, int n_in,
                              void* d_out, int out_size)
{
    const float* x  = (const float*)d_in[0];
    const int*   ei = (const int*)d_in[1];
    const float* ea = (const float*)d_in[2];
    const float* Wi = (const float*)d_in[3];
    const float* bi = (const float*)d_in[4];
    const float* Wl[3] = { (const float*)d_in[5], (const float*)d_in[7], (const float*)d_in[9] };
    const float* bl[3] = { (const float*)d_in[6], (const float*)d_in[8], (const float*)d_in[10] };
    float* out = (float*)d_out;

    const int* src = ei;
    const int* tgt = ei + N_EDGES;

    const int IN_BLOCKS    = (N_NODES + 127) / 128;             // 782
    const int LAYER_BLOCKS = (N_NODES + 63) / 64;               // 1563
    const int EDGE_BLOCKS  = (N_EDGES + 255) / 256;             // 6250
    const int SMEM_IN = IN_DIM * NPAD * 4;                      // 67584 B

    cudaFuncSetAttribute(gemm_in_kernel,
                         cudaFuncAttributeMaxDynamicSharedMemorySize, SMEM_IN);

    gemm_in_kernel<<<IN_BLOCKS, 256, SMEM_IN>>>(x, Wi, bi, tgt, out); // 1 (+hist)
    scanA_kernel<<<NSCAN, SCAN_B>>>();                                // 2 (+scanB)
    fill_kernel<<<EDGE_BLOCKS, 256>>>(src, tgt, ea);                  // 3

    for (int l = 0; l < 3; l++) {                                     // 4,5,6
        const float* hprev = out + (size_t)l * SZ;
        float* hnext = out + (size_t)(l + 1) * SZ;
        layer_kernel<<<LAYER_BLOCKS, 256>>>(hprev, Wl[l], bl[l],
                                            hnext, l & 1, l == 2);
    }
}